// round 1
// baseline (speedup 1.0000x reference)
#include <cuda_runtime.h>
#include <cuda_bf16.h>
#include <mma.h>

using namespace nvcuda;

#define N 8192
#define D 1024
#define BM 64
#define BN 64
#define BK 128
#define LDA (D + 8)    // bf16 elems, A shared leading dim (pad to shift banks)
#define LDB (BK + 8)   // bf16 elems, B shared leading dim
#define LDS (BN + 8)   // f32 elems, sim staging leading dim
#define MARGINF 1.0f

// Device scratch (no allocations allowed in kernel_launch)
__device__ __nv_bfloat16 g_imgn[(size_t)N * D];  // 16 MB
__device__ __nv_bfloat16 g_txtn[(size_t)N * D];  // 16 MB
__device__ float g_pos[N];
__device__ float g_rowsum[N];

// ---------------------------------------------------------------------------
// Kernel 1: fused L2-normalize (bf16 out) + exact fp32 positives
// one block per row, 256 threads, D=1024 -> exactly one float4 per thread
// ---------------------------------------------------------------------------
__global__ void norm_kernel(const float* __restrict__ img,
                            const float* __restrict__ txt) {
    const int row = blockIdx.x;
    const int t = threadIdx.x;

    const float4 a = reinterpret_cast<const float4*>(img + (size_t)row * D)[t];
    const float4 b = reinterpret_cast<const float4*>(txt + (size_t)row * D)[t];

    float sii = a.x * a.x + a.y * a.y + a.z * a.z + a.w * a.w;
    float stt = b.x * b.x + b.y * b.y + b.z * b.z + b.w * b.w;
    float sit = a.x * b.x + a.y * b.y + a.z * b.z + a.w * b.w;

    #pragma unroll
    for (int o = 16; o; o >>= 1) {
        sii += __shfl_xor_sync(0xffffffffu, sii, o);
        stt += __shfl_xor_sync(0xffffffffu, stt, o);
        sit += __shfl_xor_sync(0xffffffffu, sit, o);
    }

    __shared__ float w0[8], w1[8], w2[8], bc[3];
    if ((t & 31) == 0) { w0[t >> 5] = sii; w1[t >> 5] = stt; w2[t >> 5] = sit; }
    __syncthreads();
    if (t == 0) {
        float a0 = 0.f, a1 = 0.f, a2 = 0.f;
        #pragma unroll
        for (int i = 0; i < 8; i++) { a0 += w0[i]; a1 += w1[i]; a2 += w2[i]; }
        bc[0] = a0; bc[1] = a1; bc[2] = a2;
    }
    __syncthreads();

    const float inv_i = 1.0f / fmaxf(sqrtf(bc[0]), 1e-12f);
    const float inv_t = 1.0f / fmaxf(sqrtf(bc[1]), 1e-12f);

    __nv_bfloat162 i01 = __floats2bfloat162_rn(a.x * inv_i, a.y * inv_i);
    __nv_bfloat162 i23 = __floats2bfloat162_rn(a.z * inv_i, a.w * inv_i);
    __nv_bfloat162 t01 = __floats2bfloat162_rn(b.x * inv_t, b.y * inv_t);
    __nv_bfloat162 t23 = __floats2bfloat162_rn(b.z * inv_t, b.w * inv_t);

    uint2 pi, pt;
    pi.x = *reinterpret_cast<unsigned int*>(&i01);
    pi.y = *reinterpret_cast<unsigned int*>(&i23);
    pt.x = *reinterpret_cast<unsigned int*>(&t01);
    pt.y = *reinterpret_cast<unsigned int*>(&t23);

    *reinterpret_cast<uint2*>(g_imgn + (size_t)row * D + t * 4) = pi;
    *reinterpret_cast<uint2*>(g_txtn + (size_t)row * D + t * 4) = pt;

    if (t == 0) g_pos[row] = bc[2] * inv_i * inv_t;  // exact fp32 diagonal
}

// ---------------------------------------------------------------------------
// Kernel 2: fused GEMM (bf16 WMMA, fp32 accum) + exp(sim-1) row-sum.
// One CTA owns 64 rows, streams all 8192 columns. A strip resident in shared.
// 256 threads = 8 warps in 4(row) x 2(col) layout; each warp: 16x32 of the tile.
// ---------------------------------------------------------------------------
__global__ __launch_bounds__(256, 1) void gemm_lse_kernel() {
    extern __shared__ __nv_bfloat16 sA[];             // [BM][LDA]  132 KB
    __shared__ __nv_bfloat16 sB[BN * LDB];            // [n=64][k=136] 17.4 KB
    __shared__ float sSim[BM * LDS];                  // [64][72]  18.4 KB
    __shared__ float rowAcc[BM];

    const int tid = threadIdx.x;
    const int bid = blockIdx.x;
    const int warp = tid >> 5;
    const int wr = warp & 3;   // row strip within 64x64 tile
    const int wc = warp >> 2;  // col strip (0/1)

    // Load resident A strip (64 x 1024 bf16), vectorized 16B
    const uint4* gA = reinterpret_cast<const uint4*>(g_imgn + (size_t)bid * BM * D);
    #pragma unroll
    for (int i = 0; i < (BM * D / 8) / 256; i++) {    // 32 iters
        int idx = tid + i * 256;
        int r = idx >> 7;            // / (D/8)
        int kk = (idx & 127) << 3;
        *reinterpret_cast<uint4*>(sA + r * LDA + kk) = gA[idx];
    }
    if (tid < BM) rowAcc[tid] = 0.0f;
    __syncthreads();

    for (int ct = 0; ct < N / BN; ct++) {
        wmma::fragment<wmma::accumulator, 16, 16, 16, float> acc0, acc1;
        wmma::fill_fragment(acc0, 0.0f);
        wmma::fill_fragment(acc1, 0.0f);

        const uint4* gB = reinterpret_cast<const uint4*>(g_txtn + (size_t)ct * BN * D);

        for (int kc = 0; kc < D / BK; kc++) {
            __syncthreads();   // prior compute / reduce done before sB overwrite
            // Stage B chunk: n in [0,64), k in [kc*128, kc*128+128)
            #pragma unroll
            for (int i = 0; i < (BN * BK / 8) / 256; i++) {  // 4 iters
                int idx = tid + i * 256;
                int n = idx >> 4;            // / (BK/8)
                int kk = (idx & 15) << 3;
                *reinterpret_cast<uint4*>(sB + n * LDB + kk) =
                    gB[n * (D / 8) + kc * (BK / 8) + (kk >> 3)];
            }
            __syncthreads();

            #pragma unroll
            for (int k4 = 0; k4 < BK / 16; k4++) {
                wmma::fragment<wmma::matrix_a, 16, 16, 16, __nv_bfloat16, wmma::row_major> fa;
                wmma::fragment<wmma::matrix_b, 16, 16, 16, __nv_bfloat16, wmma::col_major> fb0, fb1;
                wmma::load_matrix_sync(fa, sA + (wr * 16) * LDA + kc * BK + k4 * 16, LDA);
                wmma::load_matrix_sync(fb0, sB + (wc * 32) * LDB + k4 * 16, LDB);
                wmma::load_matrix_sync(fb1, sB + (wc * 32 + 16) * LDB + k4 * 16, LDB);
                wmma::mma_sync(acc0, fa, fb0, acc0);
                wmma::mma_sync(acc1, fa, fb1, acc1);
            }
        }

        // Epilogue: exp(sim - margin) elementwise (position-free), stage, row-reduce
        #pragma unroll
        for (int i = 0; i < acc0.num_elements; i++) {
            acc0.x[i] = __expf(acc0.x[i] - MARGINF);
            acc1.x[i] = __expf(acc1.x[i] - MARGINF);
        }
        wmma::store_matrix_sync(sSim + (wr * 16) * LDS + wc * 32, acc0, LDS, wmma::mem_row_major);
        wmma::store_matrix_sync(sSim + (wr * 16) * LDS + wc * 32 + 16, acc1, LDS, wmma::mem_row_major);
        __syncthreads();

        const int r = tid >> 2;
        const int q = tid & 3;
        float s = 0.0f;
        #pragma unroll
        for (int j = 0; j < 16; j++) s += sSim[r * LDS + q * 16 + j];
        s += __shfl_xor_sync(0xffffffffu, s, 1);
        s += __shfl_xor_sync(0xffffffffu, s, 2);
        if (q == 0) rowAcc[r] += s;   // unique writer per row; sync at loop top
    }

    __syncthreads();
    if (tid < BM) g_rowsum[bid * BM + tid] = rowAcc[tid];
}

// ---------------------------------------------------------------------------
// Kernel 3: loss = mean(log(rowsum) - positives)
// ---------------------------------------------------------------------------
__global__ void finalize_kernel(float* __restrict__ out) {
    __shared__ float red[256];
    float s = 0.0f;
    for (int i = threadIdx.x; i < N; i += 256)
        s += logf(g_rowsum[i]) - g_pos[i];
    red[threadIdx.x] = s;
    __syncthreads();
    #pragma unroll
    for (int off = 128; off > 0; off >>= 1) {
        if (threadIdx.x < off) red[threadIdx.x] += red[threadIdx.x + off];
        __syncthreads();
    }
    if (threadIdx.x == 0) out[0] = red[0] / (float)N;
}

// ---------------------------------------------------------------------------
extern "C" void kernel_launch(void* const* d_in, const int* in_sizes, int n_in,
                              void* d_out, int out_size) {
    const float* img = (const float*)d_in[0];
    const float* txt = (const float*)d_in[1];
    float* out = (float*)d_out;

    norm_kernel<<<N, 256>>>(img, txt);

    cudaFuncSetAttribute(gemm_lse_kernel,
                         cudaFuncAttributeMaxDynamicSharedMemorySize,
                         BM * LDA * (int)sizeof(__nv_bfloat16));
    gemm_lse_kernel<<<N / BM, 256, BM * LDA * (int)sizeof(__nv_bfloat16)>>>();

    finalize_kernel<<<1, 256>>>(out);
}

// round 3
// speedup vs baseline: 2.8657x; 2.8657x over previous
#include <cuda_runtime.h>
#include <cuda_bf16.h>
#include <cstdint>

#define NROW 8192
#define DDIM 1024
#define CH 64                   // K per pipeline chunk
#define KCH (DDIM / CH)         // 16 chunks
#define STAGES 3
#define TILE 128                // 128x128 CTA tile
#define NT (NROW / TILE)        // 64 tiles per dim
#define STG_A 16384             // 128 rows * 128 B
#define STG_BYTES 32768         // A + B per stage
#define MARGINF 1.0f

// ---------------- device scratch ----------------
__device__ __nv_bfloat16 g_imgn[(size_t)NROW * DDIM];  // 16 MB, row-major
__device__ __nv_bfloat16 g_txtn[(size_t)NROW * DDIM];  // 16 MB, row-major
__device__ float g_pos[NROW];
__device__ float g_partial[(size_t)NT * NROW];         // [ntile][row], 2 MB
__device__ float g_lse[NROW];

// ---------------- PTX helpers ----------------
__device__ __forceinline__ uint32_t smem_u32(const void* p) {
    uint32_t a;
    asm("{ .reg .u64 t; cvta.to.shared.u64 t, %1; cvt.u32.u64 %0, t; }" : "=r"(a) : "l"(p));
    return a;
}
__device__ __forceinline__ void cp16(uint32_t dst, const void* src) {
    asm volatile("cp.async.cg.shared.global [%0], [%1], 16;" :: "r"(dst), "l"(src));
}
__device__ __forceinline__ void cp_commit() {
    asm volatile("cp.async.commit_group;");
}
template <int NMAX>
__device__ __forceinline__ void cp_wait() {
    asm volatile("cp.async.wait_group %0;" :: "n"(NMAX));
}
__device__ __forceinline__ void ldsm_x4(uint32_t& r0, uint32_t& r1, uint32_t& r2, uint32_t& r3,
                                        uint32_t addr) {
    asm volatile("ldmatrix.sync.aligned.m8n8.x4.shared.b16 {%0,%1,%2,%3}, [%4];"
                 : "=r"(r0), "=r"(r1), "=r"(r2), "=r"(r3) : "r"(addr));
}
__device__ __forceinline__ void mma16816(float& c0, float& c1, float& c2, float& c3,
                                         uint32_t a0, uint32_t a1, uint32_t a2, uint32_t a3,
                                         uint32_t b0, uint32_t b1) {
    asm volatile(
        "mma.sync.aligned.m16n8k16.row.col.f32.bf16.bf16.f32 "
        "{%0,%1,%2,%3}, {%4,%5,%6,%7}, {%8,%9}, {%0,%1,%2,%3};"
        : "+f"(c0), "+f"(c1), "+f"(c2), "+f"(c3)
        : "r"(a0), "r"(a1), "r"(a2), "r"(a3), "r"(b0), "r"(b1));
}

// ---------------------------------------------------------------------------
// Kernel 1: L2-normalize -> bf16 row-major + exact fp32 positives.
// one block per row; 256 threads * float4 covers D=1024.
// ---------------------------------------------------------------------------
__global__ void norm_kernel(const float* __restrict__ img,
                            const float* __restrict__ txt) {
    const int row = blockIdx.x;
    const int t = threadIdx.x;

    const float4 a = reinterpret_cast<const float4*>(img + (size_t)row * DDIM)[t];
    const float4 b = reinterpret_cast<const float4*>(txt + (size_t)row * DDIM)[t];

    float sii = a.x * a.x + a.y * a.y + a.z * a.z + a.w * a.w;
    float stt = b.x * b.x + b.y * b.y + b.z * b.z + b.w * b.w;
    float sit = a.x * b.x + a.y * b.y + a.z * b.z + a.w * b.w;

    #pragma unroll
    for (int o = 16; o; o >>= 1) {
        sii += __shfl_xor_sync(0xffffffffu, sii, o);
        stt += __shfl_xor_sync(0xffffffffu, stt, o);
        sit += __shfl_xor_sync(0xffffffffu, sit, o);
    }

    __shared__ float w0[8], w1[8], w2[8], bc[3];
    if ((t & 31) == 0) { w0[t >> 5] = sii; w1[t >> 5] = stt; w2[t >> 5] = sit; }
    __syncthreads();
    if (t == 0) {
        float a0 = 0.f, a1 = 0.f, a2 = 0.f;
        #pragma unroll
        for (int i = 0; i < 8; i++) { a0 += w0[i]; a1 += w1[i]; a2 += w2[i]; }
        bc[0] = a0; bc[1] = a1; bc[2] = a2;
    }
    __syncthreads();

    const float inv_i = 1.0f / fmaxf(sqrtf(bc[0]), 1e-12f);
    const float inv_t = 1.0f / fmaxf(sqrtf(bc[1]), 1e-12f);

    __nv_bfloat162 i01 = __floats2bfloat162_rn(a.x * inv_i, a.y * inv_i);
    __nv_bfloat162 i23 = __floats2bfloat162_rn(a.z * inv_i, a.w * inv_i);
    __nv_bfloat162 t01 = __floats2bfloat162_rn(b.x * inv_t, b.y * inv_t);
    __nv_bfloat162 t23 = __floats2bfloat162_rn(b.z * inv_t, b.w * inv_t);

    uint2 pi, pt;
    pi.x = *reinterpret_cast<unsigned int*>(&i01);
    pi.y = *reinterpret_cast<unsigned int*>(&i23);
    pt.x = *reinterpret_cast<unsigned int*>(&t01);
    pt.y = *reinterpret_cast<unsigned int*>(&t23);

    *reinterpret_cast<uint2*>(g_imgn + (size_t)row * DDIM + t * 4) = pi;
    *reinterpret_cast<uint2*>(g_txtn + (size_t)row * DDIM + t * 4) = pt;

    if (t == 0) g_pos[row] = bc[2] * inv_i * inv_t;  // exact fp32 diagonal
}

// ---------------------------------------------------------------------------
// Kernel 2: pipelined mma.sync bf16 GEMM (fp32 acc) + fused exp(sim-1) rowsum.
// CTA: 128x128 tile. 8 warps = 2(m) x 4(n); warp tile 64x32.
// smem stage: A[128][64] + B[128][64] bf16, XOR-swizzled 16B groups.
// ---------------------------------------------------------------------------
__global__ __launch_bounds__(256, 1) void gemm_lse_kernel() {
    extern __shared__ __align__(128) char smem[];      // STAGES * 32 KB
    __shared__ float rowAcc[TILE];

    const int tid = threadIdx.x;
    const int warp = tid >> 5;
    const int lane = tid & 31;
    const int wm = warp >> 2;       // 0..1
    const int wn = warp & 3;        // 0..3
    const int row0 = blockIdx.x * TILE;
    const int col0 = blockIdx.y * TILE;

    const uint32_t sbase = smem_u32(smem);
    if (tid < TILE) rowAcc[tid] = 0.0f;

    // per-thread load coords: 4 lines per operand per stage
    // line id = tid + i*256 ; r = id>>3 (0..127), g = id&7 (16B group)
    const __nv_bfloat16* gA = g_imgn + (size_t)row0 * DDIM;
    const __nv_bfloat16* gB = g_txtn + (size_t)col0 * DDIM;

    auto load_stage = [&](int chunk, int s) {
        const uint32_t st = sbase + (uint32_t)s * STG_BYTES;
        #pragma unroll
        for (int i = 0; i < 4; i++) {
            const int id = tid + i * 256;
            const int r = id >> 3;
            const int g = id & 7;
            const uint32_t sw = (uint32_t)r * 128u + (uint32_t)((g ^ (r & 7)) << 4);
            cp16(st + sw,          gA + (size_t)r * DDIM + chunk * CH + g * 8);
            cp16(st + STG_A + sw,  gB + (size_t)r * DDIM + chunk * CH + g * 8);
        }
        cp_commit();
    };

    // prologue
    #pragma unroll
    for (int c = 0; c < STAGES - 1; c++) load_stage(c, c);

    float acc[4][4][4];
    #pragma unroll
    for (int mi = 0; mi < 4; mi++)
        #pragma unroll
        for (int ni = 0; ni < 4; ni++)
            #pragma unroll
            for (int e = 0; e < 4; e++) acc[mi][ni][e] = 0.0f;

    for (int c = 0; c < KCH; c++) {
        cp_wait<STAGES - 2>();
        __syncthreads();

        // issue next chunk's loads (overlap with this chunk's math)
        const int nx = c + STAGES - 1;
        if (nx < KCH) load_stage(nx, nx % STAGES);
        else cp_commit();   // keep group accounting consistent

        const uint32_t sa = sbase + (uint32_t)(c % STAGES) * STG_BYTES;
        const uint32_t sb = sa + STG_A;

        #pragma unroll
        for (int ks = 0; ks < 4; ks++) {
            uint32_t a[4][4], b[2][4];
            // A: 4 m16 tiles; lanes 0-15 -> rows, lanes 16-31 -> k-high group
            #pragma unroll
            for (int mi = 0; mi < 4; mi++) {
                const int r = wm * 64 + mi * 16 + (lane & 15);
                const int g = 2 * ks + (lane >> 4);
                ldsm_x4(a[mi][0], a[mi][1], a[mi][2], a[mi][3],
                        sa + (uint32_t)r * 128u + (uint32_t)((g ^ (r & 7)) << 4));
            }
            // B: 2 x4-ldmatrix cover 4 n8 tiles
            #pragma unroll
            for (int bi = 0; bi < 2; bi++) {
                const int r = col0 ? 0 : 0, dummy = r;  (void)dummy;
                const int nr = wn * 32 + bi * 16 + (lane & 7) + ((lane >> 4) << 3);
                const int g = 2 * ks + ((lane >> 3) & 1);
                ldsm_x4(b[bi][0], b[bi][1], b[bi][2], b[bi][3],
                        sb + (uint32_t)nr * 128u + (uint32_t)((g ^ (nr & 7)) << 4));
            }
            #pragma unroll
            for (int mi = 0; mi < 4; mi++)
                #pragma unroll
                for (int ni = 0; ni < 4; ni++)
                    mma16816(acc[mi][ni][0], acc[mi][ni][1], acc[mi][ni][2], acc[mi][ni][3],
                             a[mi][0], a[mi][1], a[mi][2], a[mi][3],
                             b[ni >> 1][(ni & 1) * 2], b[ni >> 1][(ni & 1) * 2 + 1]);
        }
        __syncthreads();
    }

    // Epilogue: exp(sim - margin), reduce rows. d frag: c0/c1 row g=lane/4,
    // c2/c3 row g+8; cols vary with lane%4 -> quad shfl reduce.
    #pragma unroll
    for (int mi = 0; mi < 4; mi++) {
        float s0 = 0.0f, s1 = 0.0f;
        #pragma unroll
        for (int ni = 0; ni < 4; ni++) {
            s0 += __expf(acc[mi][ni][0] - MARGINF) + __expf(acc[mi][ni][1] - MARGINF);
            s1 += __expf(acc[mi][ni][2] - MARGINF) + __expf(acc[mi][ni][3] - MARGINF);
        }
        s0 += __shfl_xor_sync(0xffffffffu, s0, 1);
        s0 += __shfl_xor_sync(0xffffffffu, s0, 2);
        s1 += __shfl_xor_sync(0xffffffffu, s1, 1);
        s1 += __shfl_xor_sync(0xffffffffu, s1, 2);
        if ((lane & 3) == 0) {
            const int r = wm * 64 + mi * 16 + (lane >> 2);
            atomicAdd(&rowAcc[r], s0);
            atomicAdd(&rowAcc[r + 8], s1);
        }
    }
    __syncthreads();
    if (tid < TILE)
        g_partial[(size_t)blockIdx.y * NROW + row0 + tid] = rowAcc[tid];
}

// ---------------------------------------------------------------------------
// Kernel 3a: per-row lse = log(sum of NT partials) - pos
// ---------------------------------------------------------------------------
__global__ void finalize1_kernel() {
    const int row = blockIdx.x * 256 + threadIdx.x;
    float s = 0.0f;
    #pragma unroll
    for (int p = 0; p < NT; p++) s += g_partial[(size_t)p * NROW + row];
    g_lse[row] = logf(s) - g_pos[row];
}

// ---------------------------------------------------------------------------
// Kernel 3b: mean over rows
// ---------------------------------------------------------------------------
__global__ void finalize2_kernel(float* __restrict__ out) {
    __shared__ float red[256];
    float s = 0.0f;
    for (int i = threadIdx.x; i < NROW; i += 256) s += g_lse[i];
    red[threadIdx.x] = s;
    __syncthreads();
    #pragma unroll
    for (int off = 128; off > 0; off >>= 1) {
        if (threadIdx.x < off) red[threadIdx.x] += red[threadIdx.x + off];
        __syncthreads();
    }
    if (threadIdx.x == 0) out[0] = red[0] / (float)NROW;
}

// ---------------------------------------------------------------------------
extern "C" void kernel_launch(void* const* d_in, const int* in_sizes, int n_in,
                              void* d_out, int out_size) {
    const float* img = (const float*)d_in[0];
    const float* txt = (const float*)d_in[1];
    float* out = (float*)d_out;

    norm_kernel<<<NROW, 256>>>(img, txt);

    cudaFuncSetAttribute(gemm_lse_kernel,
                         cudaFuncAttributeMaxDynamicSharedMemorySize,
                         STAGES * STG_BYTES);
    dim3 grid(NT, NT);
    gemm_lse_kernel<<<grid, 256, STAGES * STG_BYTES>>>();

    finalize1_kernel<<<NROW / 256, 256>>>();
    finalize2_kernel<<<1, 256>>>(out);
}

// round 4
// speedup vs baseline: 3.6974x; 1.2902x over previous
#include <cuda_runtime.h>
#include <cuda_bf16.h>
#include <cstdint>

#define NROW 8192
#define DDIM 1024
#define CH 64                     // K per pipeline chunk (64 bf16 = 128 B)
#define KCH (DDIM / CH)           // 16 chunks
#define STAGES 3
#define TM 128                    // CTA tile M
#define TN 256                    // CTA tile N
#define NTM (NROW / TM)           // 64
#define NTN (NROW / TN)           // 32
#define STG_A (TM * 128)          // 16 KB
#define STG_B (TN * 128)          // 32 KB
#define STG_BYTES (STG_A + STG_B) // 48 KB
#define CHUNK_STRIDE ((size_t)NROW * 128)  // 1 MB per k-chunk blob
#define MARGINF 1.0f

// ---------------- device scratch ----------------
__device__ __nv_bfloat16 g_imgn[(size_t)NROW * DDIM];  // chunk-major swizzled, 16 MB
__device__ __nv_bfloat16 g_txtn[(size_t)NROW * DDIM];  // chunk-major swizzled, 16 MB
__device__ float g_pos[NROW];
__device__ float g_partial[(size_t)NTN * NROW];        // [ntile][row]
__device__ float g_lse[NROW];

// ---------------- PTX helpers ----------------
__device__ __forceinline__ uint32_t smem_u32(const void* p) {
    uint32_t a;
    asm("{ .reg .u64 t; cvta.to.shared.u64 t, %1; cvt.u32.u64 %0, t; }" : "=r"(a) : "l"(p));
    return a;
}
__device__ __forceinline__ void mbar_init(uint32_t a, uint32_t c) {
    asm volatile("mbarrier.init.shared.b64 [%0], %1;" :: "r"(a), "r"(c) : "memory");
}
__device__ __forceinline__ void mbar_inval(uint32_t a) {
    asm volatile("mbarrier.inval.shared.b64 [%0];" :: "r"(a) : "memory");
}
__device__ __forceinline__ void mbar_expect_tx(uint32_t a, uint32_t tx) {
    asm volatile("mbarrier.arrive.expect_tx.shared.b64 _, [%0], %1;" :: "r"(a), "r"(tx) : "memory");
}
__device__ __forceinline__ void mbar_wait(uint32_t a, uint32_t parity) {
    asm volatile(
        "{\n\t.reg .pred P;\n\t"
        "WL_%=:\n\t"
        "mbarrier.try_wait.parity.shared.b64 P, [%0], %1;\n\t"
        "@!P bra WL_%=;\n\t}"
        :: "r"(a), "r"(parity) : "memory");
}
__device__ __forceinline__ void bulk_g2s(uint32_t dst, const void* src, uint32_t bytes, uint32_t mbar) {
    asm volatile(
        "cp.async.bulk.shared::cluster.global.mbarrier::complete_tx::bytes [%0], [%1], %2, [%3];"
        :: "r"(dst), "l"(src), "r"(bytes), "r"(mbar) : "memory");
}
__device__ __forceinline__ void ldsm_x4(uint32_t& r0, uint32_t& r1, uint32_t& r2, uint32_t& r3,
                                        uint32_t addr) {
    asm volatile("ldmatrix.sync.aligned.m8n8.x4.shared.b16 {%0,%1,%2,%3}, [%4];"
                 : "=r"(r0), "=r"(r1), "=r"(r2), "=r"(r3) : "r"(addr));
}
__device__ __forceinline__ void mma16816(float& c0, float& c1, float& c2, float& c3,
                                         uint32_t a0, uint32_t a1, uint32_t a2, uint32_t a3,
                                         uint32_t b0, uint32_t b1) {
    asm volatile(
        "mma.sync.aligned.m16n8k16.row.col.f32.bf16.bf16.f32 "
        "{%0,%1,%2,%3}, {%4,%5,%6,%7}, {%8,%9}, {%0,%1,%2,%3};"
        : "+f"(c0), "+f"(c1), "+f"(c2), "+f"(c3)
        : "r"(a0), "r"(a1), "r"(a2), "r"(a3), "r"(b0), "r"(b1));
}

// ---------------------------------------------------------------------------
// Kernel 1: L2-normalize -> bf16, chunk-major + XOR-swizzled layout, fp32 pos.
// byte addr = chunk*CHUNK_STRIDE + row*128 + col_in_chunk*2, then
// off ^= (off>>3)&0x70  (same pattern ldmatrix consumer uses; 8B granule safe)
// ---------------------------------------------------------------------------
__global__ void norm_kernel(const float* __restrict__ img,
                            const float* __restrict__ txt) {
    const int row = blockIdx.x;
    const int t = threadIdx.x;

    const float4 a = reinterpret_cast<const float4*>(img + (size_t)row * DDIM)[t];
    const float4 b = reinterpret_cast<const float4*>(txt + (size_t)row * DDIM)[t];

    float sii = a.x * a.x + a.y * a.y + a.z * a.z + a.w * a.w;
    float stt = b.x * b.x + b.y * b.y + b.z * b.z + b.w * b.w;
    float sit = a.x * b.x + a.y * b.y + a.z * b.z + a.w * b.w;

    #pragma unroll
    for (int o = 16; o; o >>= 1) {
        sii += __shfl_xor_sync(0xffffffffu, sii, o);
        stt += __shfl_xor_sync(0xffffffffu, stt, o);
        sit += __shfl_xor_sync(0xffffffffu, sit, o);
    }

    __shared__ float w0[8], w1[8], w2[8], bc[3];
    if ((t & 31) == 0) { w0[t >> 5] = sii; w1[t >> 5] = stt; w2[t >> 5] = sit; }
    __syncthreads();
    if (t == 0) {
        float a0 = 0.f, a1 = 0.f, a2 = 0.f;
        #pragma unroll
        for (int i = 0; i < 8; i++) { a0 += w0[i]; a1 += w1[i]; a2 += w2[i]; }
        bc[0] = a0; bc[1] = a1; bc[2] = a2;
    }
    __syncthreads();

    const float inv_i = 1.0f / fmaxf(sqrtf(bc[0]), 1e-12f);
    const float inv_t = 1.0f / fmaxf(sqrtf(bc[1]), 1e-12f);

    __nv_bfloat162 i01 = __floats2bfloat162_rn(a.x * inv_i, a.y * inv_i);
    __nv_bfloat162 i23 = __floats2bfloat162_rn(a.z * inv_i, a.w * inv_i);
    __nv_bfloat162 t01 = __floats2bfloat162_rn(b.x * inv_t, b.y * inv_t);
    __nv_bfloat162 t23 = __floats2bfloat162_rn(b.z * inv_t, b.w * inv_t);

    uint2 pi, pt;
    pi.x = *reinterpret_cast<unsigned int*>(&i01);
    pi.y = *reinterpret_cast<unsigned int*>(&i23);
    pt.x = *reinterpret_cast<unsigned int*>(&t01);
    pt.y = *reinterpret_cast<unsigned int*>(&t23);

    const int c = t >> 4;                // k-chunk (64 cols each)
    const int ci = (t & 15) << 2;        // col within chunk (4 bf16)
    uint32_t off = (uint32_t)row * 128u + (uint32_t)ci * 2u;
    off ^= (off >> 3) & 0x70u;
    const size_t addr = (size_t)c * CHUNK_STRIDE + off;

    *reinterpret_cast<uint2*>(reinterpret_cast<char*>(g_imgn) + addr) = pi;
    *reinterpret_cast<uint2*>(reinterpret_cast<char*>(g_txtn) + addr) = pt;

    if (t == 0) g_pos[row] = bc[2] * inv_i * inv_t;  // exact fp32 diagonal
}

// ---------------------------------------------------------------------------
// Kernel 2: bulk-async pipelined mma.sync bf16 GEMM + fused exp(sim-1) rowsum.
// CTA tile 128x256, 8 warps = 2(m) x 4(n), warp tile 64x64.
// 3-stage pipeline, 2 cp.async.bulk per stage (single-thread issue).
// ---------------------------------------------------------------------------
__global__ __launch_bounds__(256, 1) void gemm_lse_kernel() {
    extern __shared__ __align__(128) char smem[];       // STAGES*48KB (+pad)
    __shared__ __align__(8) unsigned long long full_bar[STAGES];
    __shared__ float rowAcc[TM];

    const int tid = threadIdx.x;
    const int warp = tid >> 5;
    const int lane = tid & 31;
    const int wm = warp >> 2;        // 0..1
    const int wn = warp & 3;         // 0..3
    const int mtile = blockIdx.x;    // 64
    const int ntile = blockIdx.y;    // 32

    uint32_t sbase = smem_u32(smem);
    sbase = (sbase + 127u) & ~127u;
    const uint32_t fullb = smem_u32(&full_bar[0]);

    if (tid == 0) {
        #pragma unroll
        for (int s = 0; s < STAGES; s++) mbar_init(fullb + 8u * s, 1);
    }
    if (tid < TM) rowAcc[tid] = 0.0f;
    __syncthreads();

    const char* baseA = reinterpret_cast<const char*>(g_imgn) + (size_t)mtile * STG_A;
    const char* baseB = reinterpret_cast<const char*>(g_txtn) + (size_t)ntile * STG_B;

    // prologue: chunks 0..STAGES-2
    if (tid == 0) {
        #pragma unroll
        for (int c = 0; c < STAGES - 1; c++) {
            const uint32_t st = sbase + (uint32_t)c * STG_BYTES;
            mbar_expect_tx(fullb + 8u * c, STG_BYTES);
            bulk_g2s(st,         baseA + (size_t)c * CHUNK_STRIDE, STG_A, fullb + 8u * c);
            bulk_g2s(st + STG_A, baseB + (size_t)c * CHUNK_STRIDE, STG_B, fullb + 8u * c);
        }
    }

    float acc[4][8][4];
    #pragma unroll
    for (int mi = 0; mi < 4; mi++)
        #pragma unroll
        for (int ni = 0; ni < 8; ni++)
            #pragma unroll
            for (int e = 0; e < 4; e++) acc[mi][ni][e] = 0.0f;

    for (int c = 0; c < KCH; c++) {
        const int s = c % STAGES;
        mbar_wait(fullb + 8u * s, (uint32_t)((c / STAGES) & 1));
        __syncthreads();   // all warps done with slot (c-1)%STAGES -> reusable

        if (tid == 0) {
            const int nx = c + STAGES - 1;
            if (nx < KCH) {
                const int sn = nx % STAGES;
                const uint32_t st = sbase + (uint32_t)sn * STG_BYTES;
                mbar_expect_tx(fullb + 8u * sn, STG_BYTES);
                bulk_g2s(st,         baseA + (size_t)nx * CHUNK_STRIDE, STG_A, fullb + 8u * sn);
                bulk_g2s(st + STG_A, baseB + (size_t)nx * CHUNK_STRIDE, STG_B, fullb + 8u * sn);
            }
        }

        const uint32_t sa = sbase + (uint32_t)s * STG_BYTES;
        const uint32_t sb = sa + STG_A;

        #pragma unroll
        for (int ks = 0; ks < 4; ks++) {
            uint32_t a[4][4], b[4][4];
            #pragma unroll
            for (int mi = 0; mi < 4; mi++) {
                const int r = wm * 64 + mi * 16 + (lane & 15);
                const int g = 2 * ks + (lane >> 4);
                ldsm_x4(a[mi][0], a[mi][1], a[mi][2], a[mi][3],
                        sa + (uint32_t)r * 128u + (uint32_t)((g ^ (r & 7)) << 4));
            }
            #pragma unroll
            for (int bi = 0; bi < 4; bi++) {
                const int nr = wn * 64 + bi * 16 + (lane & 7) + ((lane >> 4) << 3);
                const int g = 2 * ks + ((lane >> 3) & 1);
                ldsm_x4(b[bi][0], b[bi][1], b[bi][2], b[bi][3],
                        sb + (uint32_t)nr * 128u + (uint32_t)((g ^ (nr & 7)) << 4));
            }
            #pragma unroll
            for (int mi = 0; mi < 4; mi++)
                #pragma unroll
                for (int ni = 0; ni < 8; ni++)
                    mma16816(acc[mi][ni][0], acc[mi][ni][1], acc[mi][ni][2], acc[mi][ni][3],
                             a[mi][0], a[mi][1], a[mi][2], a[mi][3],
                             b[ni >> 1][(ni & 1) * 2], b[ni >> 1][(ni & 1) * 2 + 1]);
        }
    }

    // Epilogue: exp(sim - margin), per-row reduce (quad shfl + smem atomics)
    #pragma unroll
    for (int mi = 0; mi < 4; mi++) {
        float s0 = 0.0f, s1 = 0.0f;
        #pragma unroll
        for (int ni = 0; ni < 8; ni++) {
            s0 += __expf(acc[mi][ni][0] - MARGINF) + __expf(acc[mi][ni][1] - MARGINF);
            s1 += __expf(acc[mi][ni][2] - MARGINF) + __expf(acc[mi][ni][3] - MARGINF);
        }
        s0 += __shfl_xor_sync(0xffffffffu, s0, 1);
        s0 += __shfl_xor_sync(0xffffffffu, s0, 2);
        s1 += __shfl_xor_sync(0xffffffffu, s1, 1);
        s1 += __shfl_xor_sync(0xffffffffu, s1, 2);
        if ((lane & 3) == 0) {
            const int r = wm * 64 + mi * 16 + (lane >> 2);
            atomicAdd(&rowAcc[r], s0);
            atomicAdd(&rowAcc[r + 8], s1);
        }
    }
    __syncthreads();
    if (tid < TM)
        g_partial[(size_t)ntile * NROW + mtile * TM + tid] = rowAcc[tid];

    if (tid == 0) {
        #pragma unroll
        for (int s = 0; s < STAGES; s++) mbar_inval(fullb + 8u * s);
    }
}

// ---------------------------------------------------------------------------
// Kernel 3a: per-row lse = log(sum of NTN partials) - pos
// ---------------------------------------------------------------------------
__global__ void finalize1_kernel() {
    const int row = blockIdx.x * 256 + threadIdx.x;
    float s = 0.0f;
    #pragma unroll
    for (int p = 0; p < NTN; p++) s += g_partial[(size_t)p * NROW + row];
    g_lse[row] = logf(s) - g_pos[row];
}

// ---------------------------------------------------------------------------
// Kernel 3b: mean over rows
// ---------------------------------------------------------------------------
__global__ void finalize2_kernel(float* __restrict__ out) {
    __shared__ float red[256];
    float s = 0.0f;
    for (int i = threadIdx.x; i < NROW; i += 256) s += g_lse[i];
    red[threadIdx.x] = s;
    __syncthreads();
    #pragma unroll
    for (int off = 128; off > 0; off >>= 1) {
        if (threadIdx.x < off) red[threadIdx.x] += red[threadIdx.x + off];
        __syncthreads();
    }
    if (threadIdx.x == 0) out[0] = red[0] / (float)NROW;
}

// ---------------------------------------------------------------------------
extern "C" void kernel_launch(void* const* d_in, const int* in_sizes, int n_in,
                              void* d_out, int out_size) {
    const float* img = (const float*)d_in[0];
    const float* txt = (const float*)d_in[1];
    float* out = (float*)d_out;

    norm_kernel<<<NROW, 256>>>(img, txt);

    cudaFuncSetAttribute(gemm_lse_kernel,
                         cudaFuncAttributeMaxDynamicSharedMemorySize,
                         STAGES * STG_BYTES + 128);
    dim3 grid(NTM, NTN);
    gemm_lse_kernel<<<grid, 256, STAGES * STG_BYTES + 128>>>();

    finalize1_kernel<<<NROW / 256, 256>>>();
    finalize2_kernel<<<1, 256>>>(out);
}